// round 2
// baseline (speedup 1.0000x reference)
#include <cuda_runtime.h>
#include <math.h>

// Problem dims
#define BB 4
#define SS 4096
#define DD 2048            // K (contraction)
#define EE 2048            // N (output feature)
#define MM (BB*SS)         // 16384 rows
#define NCHUNK 64          // chunks per sequence
#define LCHUNK (SS/NCHUNK) // 64 steps per chunk

// Scratch (device globals — no runtime allocation allowed)
__device__ float g_q [(size_t)MM * EE];   // 128 MB
__device__ float g_kv[(size_t)MM * EE];   // 128 MB  (k*v fused in epilogue)
__device__ float g_g [(size_t)MM * EE];   // 128 MB  (sigmoid applied)
__device__ float g_sums[(size_t)BB * EE * NCHUNK]; // 2 MB chunk prefix offsets

// ---------------------------------------------------------------------------
// GEMM: C[m,n] = sum_d X[m,d] * W[n,d] + b[n]   (TN, both K-major, fp32 SIMT)
// BM=BN=128, BK=16, 256 threads, 8x8 per thread.
// ---------------------------------------------------------------------------

// z==0: q = X@Wq^T + bq        -> g_q
// z==1: g = sigmoid(X@Wg^T+bg) -> g_g
__global__ __launch_bounds__(256) void gemm_single(
    const float* __restrict__ X,
    const float* __restrict__ Wq, const float* __restrict__ bq,
    const float* __restrict__ Wg, const float* __restrict__ bg)
{
    const int z = blockIdx.z;
    const float* Wm  = z ? Wg : Wq;
    const float* bias = z ? bg : bq;
    float* out = z ? g_g : g_q;

    __shared__ float As[16][128];
    __shared__ float Bs[16][128];

    const int tid  = threadIdx.x;
    const int lrow = tid >> 2;          // 0..63
    const int lcol = (tid & 3) << 2;    // 0,4,8,12
    const int ty   = tid >> 4;          // 0..15
    const int tx   = tid & 15;          // 0..15
    const size_t m0 = (size_t)blockIdx.y * 128;
    const size_t n0 = (size_t)blockIdx.x * 128;

    const float* Ag = X  + (m0 + lrow) * (size_t)DD + lcol;
    const float* Bg = Wm + (n0 + lrow) * (size_t)DD + lcol;

    float acc[8][8];
    #pragma unroll
    for (int i = 0; i < 8; i++)
        #pragma unroll
        for (int j = 0; j < 8; j++) acc[i][j] = 0.f;

    for (int k0 = 0; k0 < DD; k0 += 16) {
        float4 a0 = *(const float4*)(Ag + k0);
        float4 a1 = *(const float4*)(Ag + k0 + 64 * (size_t)DD);
        float4 w0 = *(const float4*)(Bg + k0);
        float4 w1 = *(const float4*)(Bg + k0 + 64 * (size_t)DD);
        __syncthreads();
        As[lcol+0][lrow] = a0.x; As[lcol+1][lrow] = a0.y;
        As[lcol+2][lrow] = a0.z; As[lcol+3][lrow] = a0.w;
        As[lcol+0][lrow+64] = a1.x; As[lcol+1][lrow+64] = a1.y;
        As[lcol+2][lrow+64] = a1.z; As[lcol+3][lrow+64] = a1.w;
        Bs[lcol+0][lrow] = w0.x; Bs[lcol+1][lrow] = w0.y;
        Bs[lcol+2][lrow] = w0.z; Bs[lcol+3][lrow] = w0.w;
        Bs[lcol+0][lrow+64] = w1.x; Bs[lcol+1][lrow+64] = w1.y;
        Bs[lcol+2][lrow+64] = w1.z; Bs[lcol+3][lrow+64] = w1.w;
        __syncthreads();
        #pragma unroll
        for (int kk = 0; kk < 16; kk++) {
            float4 ra0 = *(const float4*)&As[kk][ty*8];
            float4 ra1 = *(const float4*)&As[kk][ty*8+4];
            float4 rb0 = *(const float4*)&Bs[kk][tx*8];
            float4 rb1 = *(const float4*)&Bs[kk][tx*8+4];
            float ra[8] = {ra0.x, ra0.y, ra0.z, ra0.w, ra1.x, ra1.y, ra1.z, ra1.w};
            float rb[8] = {rb0.x, rb0.y, rb0.z, rb0.w, rb1.x, rb1.y, rb1.z, rb1.w};
            #pragma unroll
            for (int i = 0; i < 8; i++)
                #pragma unroll
                for (int j = 0; j < 8; j++)
                    acc[i][j] = fmaf(ra[i], rb[j], acc[i][j]);
        }
    }

    #pragma unroll
    for (int i = 0; i < 8; i++) {
        size_t m = m0 + (size_t)ty * 8 + i;
        float* orow = out + m * (size_t)EE + n0 + (size_t)tx * 8;
        #pragma unroll
        for (int j = 0; j < 8; j++) {
            float v = acc[i][j] + bias[n0 + tx*8 + j];
            if (z) v = 1.f / (1.f + expf(-v));
            orow[j] = v;
        }
    }
}

// k and v computed in the same CTA; epilogue writes kv = (k+bk)*(v+bv)
__global__ __launch_bounds__(256) void gemm_kv(
    const float* __restrict__ X,
    const float* __restrict__ Wk, const float* __restrict__ bk,
    const float* __restrict__ Wv, const float* __restrict__ bv)
{
    __shared__ float As [16][128];
    __shared__ float Bks[16][128];
    __shared__ float Bvs[16][128];

    const int tid  = threadIdx.x;
    const int lrow = tid >> 2;
    const int lcol = (tid & 3) << 2;
    const int ty   = tid >> 4;
    const int tx   = tid & 15;
    const size_t m0 = (size_t)blockIdx.y * 128;
    const size_t n0 = (size_t)blockIdx.x * 128;

    const float* Ag  = X  + (m0 + lrow) * (size_t)DD + lcol;
    const float* Bkg = Wk + (n0 + lrow) * (size_t)DD + lcol;
    const float* Bvg = Wv + (n0 + lrow) * (size_t)DD + lcol;

    float acck[8][8], accv[8][8];
    #pragma unroll
    for (int i = 0; i < 8; i++)
        #pragma unroll
        for (int j = 0; j < 8; j++) { acck[i][j] = 0.f; accv[i][j] = 0.f; }

    for (int k0 = 0; k0 < DD; k0 += 16) {
        float4 a0 = *(const float4*)(Ag + k0);
        float4 a1 = *(const float4*)(Ag + k0 + 64 * (size_t)DD);
        float4 k0v = *(const float4*)(Bkg + k0);
        float4 k1v = *(const float4*)(Bkg + k0 + 64 * (size_t)DD);
        float4 v0v = *(const float4*)(Bvg + k0);
        float4 v1v = *(const float4*)(Bvg + k0 + 64 * (size_t)DD);
        __syncthreads();
        As[lcol+0][lrow] = a0.x; As[lcol+1][lrow] = a0.y;
        As[lcol+2][lrow] = a0.z; As[lcol+3][lrow] = a0.w;
        As[lcol+0][lrow+64] = a1.x; As[lcol+1][lrow+64] = a1.y;
        As[lcol+2][lrow+64] = a1.z; As[lcol+3][lrow+64] = a1.w;
        Bks[lcol+0][lrow] = k0v.x; Bks[lcol+1][lrow] = k0v.y;
        Bks[lcol+2][lrow] = k0v.z; Bks[lcol+3][lrow] = k0v.w;
        Bks[lcol+0][lrow+64] = k1v.x; Bks[lcol+1][lrow+64] = k1v.y;
        Bks[lcol+2][lrow+64] = k1v.z; Bks[lcol+3][lrow+64] = k1v.w;
        Bvs[lcol+0][lrow] = v0v.x; Bvs[lcol+1][lrow] = v0v.y;
        Bvs[lcol+2][lrow] = v0v.z; Bvs[lcol+3][lrow] = v0v.w;
        Bvs[lcol+0][lrow+64] = v1v.x; Bvs[lcol+1][lrow+64] = v1v.y;
        Bvs[lcol+2][lrow+64] = v1v.z; Bvs[lcol+3][lrow+64] = v1v.w;
        __syncthreads();
        #pragma unroll
        for (int kk = 0; kk < 16; kk++) {
            float4 ra0 = *(const float4*)&As[kk][ty*8];
            float4 ra1 = *(const float4*)&As[kk][ty*8+4];
            float4 rk0 = *(const float4*)&Bks[kk][tx*8];
            float4 rk1 = *(const float4*)&Bks[kk][tx*8+4];
            float4 rv0 = *(const float4*)&Bvs[kk][tx*8];
            float4 rv1 = *(const float4*)&Bvs[kk][tx*8+4];
            float ra[8] = {ra0.x, ra0.y, ra0.z, ra0.w, ra1.x, ra1.y, ra1.z, ra1.w};
            float rk[8] = {rk0.x, rk0.y, rk0.z, rk0.w, rk1.x, rk1.y, rk1.z, rk1.w};
            float rv[8] = {rv0.x, rv0.y, rv0.z, rv0.w, rv1.x, rv1.y, rv1.z, rv1.w};
            #pragma unroll
            for (int i = 0; i < 8; i++)
                #pragma unroll
                for (int j = 0; j < 8; j++) {
                    acck[i][j] = fmaf(ra[i], rk[j], acck[i][j]);
                    accv[i][j] = fmaf(ra[i], rv[j], accv[i][j]);
                }
        }
    }

    #pragma unroll
    for (int i = 0; i < 8; i++) {
        size_t m = m0 + (size_t)ty * 8 + i;
        float* orow = g_kv + m * (size_t)EE + n0 + (size_t)tx * 8;
        #pragma unroll
        for (int j = 0; j < 8; j++) {
            float kvl = (acck[i][j] + bk[n0 + tx*8 + j]) *
                        (accv[i][j] + bv[n0 + tx*8 + j]);
            orow[j] = kvl;
        }
    }
}

// ---------------------------------------------------------------------------
// Scan pass 1: per-chunk sums of kv.  thread = (b, chunk, e)
// ---------------------------------------------------------------------------
__global__ __launch_bounds__(256) void chunk_sums()
{
    const int e = blockIdx.x * 256 + threadIdx.x;  // 0..2047
    const int c = blockIdx.y;                      // chunk 0..63
    const int b = blockIdx.z;                      // batch 0..3
    const float* p = g_kv + ((size_t)(b * SS + c * LCHUNK)) * EE + e;
    float s = 0.f;
    #pragma unroll 8
    for (int i = 0; i < LCHUNK; i++) s += p[(size_t)i * EE];
    g_sums[((size_t)b * EE + e) * NCHUNK + c] = s;
}

// ---------------------------------------------------------------------------
// Scan pass 2: exclusive scan of 64 chunk sums per chain (in place)
// ---------------------------------------------------------------------------
__global__ __launch_bounds__(256) void scan_sums()
{
    const int t = blockIdx.x * 256 + threadIdx.x;  // 0..8191 (b*E + e)
    float* p = g_sums + (size_t)t * NCHUNK;
    float v[NCHUNK];
    #pragma unroll
    for (int c = 0; c < NCHUNK; c++) v[c] = p[c];
    float run = 0.f;
    #pragma unroll
    for (int c = 0; c < NCHUNK; c++) { float t2 = v[c]; v[c] = run; run += t2; }
    #pragma unroll
    for (int c = 0; c < NCHUNK; c++) p[c] = v[c];
}

// ---------------------------------------------------------------------------
// Scan pass 3: local inclusive scan + q * state * g
// ---------------------------------------------------------------------------
__global__ __launch_bounds__(256) void finalize(float* __restrict__ out)
{
    const int e = blockIdx.x * 256 + threadIdx.x;
    const int c = blockIdx.y;
    const int b = blockIdx.z;
    float run = g_sums[((size_t)b * EE + e) * NCHUNK + c];
    size_t idx = ((size_t)(b * SS + c * LCHUNK)) * EE + e;
    #pragma unroll 4
    for (int i = 0; i < LCHUNK; i++) {
        float kv = g_kv[idx];
        run += kv;
        out[idx] = g_q[idx] * run * g_g[idx];
        idx += EE;
    }
}

// ---------------------------------------------------------------------------
// Launch
// ---------------------------------------------------------------------------
extern "C" void kernel_launch(void* const* d_in, const int* in_sizes, int n_in,
                              void* d_out, int out_size)
{
    const float* x  = (const float*)d_in[0];
    const float* Wq = (const float*)d_in[1];
    const float* bq = (const float*)d_in[2];
    const float* Wk = (const float*)d_in[3];
    const float* bk = (const float*)d_in[4];
    const float* Wv = (const float*)d_in[5];
    const float* bv = (const float*)d_in[6];
    const float* Wg = (const float*)d_in[7];
    const float* bg = (const float*)d_in[8];
    float* out = (float*)d_out;

    dim3 gridS(EE / 128, MM / 128, 2);   // q and g
    gemm_single<<<gridS, 256>>>(x, Wq, bq, Wg, bg);

    dim3 gridKV(EE / 128, MM / 128);
    gemm_kv<<<gridKV, 256>>>(x, Wk, bk, Wv, bv);

    dim3 gridC(EE / 256, NCHUNK, BB);
    chunk_sums<<<gridC, 256>>>();

    scan_sums<<<(BB * EE) / 256, 256>>>();

    finalize<<<gridC, 256>>>(out);
}

// round 4
// speedup vs baseline: 3.4214x; 3.4214x over previous
#include <cuda_runtime.h>
#include <cuda_bf16.h>
#include <cstdint>
#include <math.h>

// ---------------------------------------------------------------------------
// Problem dims
// ---------------------------------------------------------------------------
#define BB 4
#define SS 4096
#define DD 2048
#define EE 2048
#define MM (BB*SS)         // 16384
#define NCHUNK 64
#define LCHUNK (SS/NCHUNK) // 64

// GEMM tiling
#define Bb_M 128
#define Bb_N 128
#define Bb_K 64            // 64 bf16 = 128 bytes per row (SW128 atom)
#define NSTAGE 3
#define KSTAGES (DD/Bb_K)  // 32

// Stage smem layout (bytes)
#define AHI_OFF 0
#define ALO_OFF 16384
#define BHI_OFF 32768
#define BLO_OFF 49152
#define STAGE_BYTES 65536
#define SMEM_TOTAL (NSTAGE*STAGE_BYTES)   // 196608

// ---------------------------------------------------------------------------
// Device scratch
// ---------------------------------------------------------------------------
__device__ __nv_bfloat16 g_xhi[(size_t)MM * DD];
__device__ __nv_bfloat16 g_xlo[(size_t)MM * DD];
__device__ __nv_bfloat16 g_whi[(size_t)4 * DD * EE];   // order: q,k,v,g
__device__ __nv_bfloat16 g_wlo[(size_t)4 * DD * EE];
__device__ float g_q[(size_t)MM * EE];
__device__ float g_k[(size_t)MM * EE];
__device__ float g_v[(size_t)MM * EE];
__device__ float g_g[(size_t)MM * EE];
__device__ float g_sums[(size_t)BB * EE * NCHUNK];

// ---------------------------------------------------------------------------
// Helpers (sm_80-era instructions only — compile at compute_103 baseline)
// ---------------------------------------------------------------------------
__device__ __forceinline__ uint32_t smem_u32(const void* p) {
    uint32_t a;
    asm("{ .reg .u64 t; cvta.to.shared.u64 t, %1; cvt.u32.u64 %0, t; }"
        : "=r"(a) : "l"(p));
    return a;
}
__device__ __forceinline__ void cp_async16(uint32_t dst, const void* src) {
    asm volatile("cp.async.cg.shared.global [%0], [%1], 16;"
                 :: "r"(dst), "l"(src) : "memory");
}
#define CP_COMMIT() asm volatile("cp.async.commit_group;" ::: "memory")
#define CP_WAIT1()  asm volatile("cp.async.wait_group 1;" ::: "memory")

__device__ __forceinline__ void ldsm4(uint32_t (&r)[4], uint32_t addr) {
    asm volatile("ldmatrix.sync.aligned.m8n8.x4.shared.b16 {%0,%1,%2,%3}, [%4];"
                 : "=r"(r[0]), "=r"(r[1]), "=r"(r[2]), "=r"(r[3]) : "r"(addr));
}
__device__ __forceinline__ void mma16816(float (&c)[4], const uint32_t (&a)[4],
                                         uint32_t b0, uint32_t b1) {
    asm volatile("mma.sync.aligned.m16n8k16.row.col.f32.bf16.bf16.f32 "
                 "{%0,%1,%2,%3}, {%4,%5,%6,%7}, {%8,%9}, {%0,%1,%2,%3};"
                 : "+f"(c[0]), "+f"(c[1]), "+f"(c[2]), "+f"(c[3])
                 : "r"(a[0]), "r"(a[1]), "r"(a[2]), "r"(a[3]), "r"(b0), "r"(b1));
}
// SW128 swizzled byte offset inside a [row][128B] tile
__device__ __forceinline__ uint32_t swz(uint32_t row, uint32_t ch) {
    return row * 128u + (((ch ^ (row & 7u)) & 7u) << 4);
}

// ---------------------------------------------------------------------------
// fp32 -> bf16 hi/lo split conversions
// ---------------------------------------------------------------------------
__global__ __launch_bounds__(256) void conv_x_kernel(const float* __restrict__ x)
{
    size_t i = ((size_t)blockIdx.x * 256 + threadIdx.x) * 4;
    float4 v = *(const float4*)(x + i);
    __nv_bfloat16 h0 = __float2bfloat16(v.x), h1 = __float2bfloat16(v.y);
    __nv_bfloat16 h2 = __float2bfloat16(v.z), h3 = __float2bfloat16(v.w);
    __nv_bfloat16 l0 = __float2bfloat16(v.x - __bfloat162float(h0));
    __nv_bfloat16 l1 = __float2bfloat16(v.y - __bfloat162float(h1));
    __nv_bfloat16 l2 = __float2bfloat16(v.z - __bfloat162float(h2));
    __nv_bfloat16 l3 = __float2bfloat16(v.w - __bfloat162float(h3));
    __nv_bfloat162* ph = (__nv_bfloat162*)(g_xhi + i);
    __nv_bfloat162* pl = (__nv_bfloat162*)(g_xlo + i);
    ph[0] = __halves2bfloat162(h0, h1); ph[1] = __halves2bfloat162(h2, h3);
    pl[0] = __halves2bfloat162(l0, l1); pl[1] = __halves2bfloat162(l2, l3);
}

__global__ __launch_bounds__(256) void conv_w_kernel(
    const float* __restrict__ Wq, const float* __restrict__ Wk,
    const float* __restrict__ Wv, const float* __restrict__ Wg)
{
    int y = blockIdx.y;
    const float* W = (y == 0) ? Wq : (y == 1) ? Wk : (y == 2) ? Wv : Wg;
    size_t base = (size_t)y * DD * EE;
    size_t i = ((size_t)blockIdx.x * 256 + threadIdx.x) * 4;
    float4 v = *(const float4*)(W + i);
    __nv_bfloat16 h0 = __float2bfloat16(v.x), h1 = __float2bfloat16(v.y);
    __nv_bfloat16 h2 = __float2bfloat16(v.z), h3 = __float2bfloat16(v.w);
    __nv_bfloat16 l0 = __float2bfloat16(v.x - __bfloat162float(h0));
    __nv_bfloat16 l1 = __float2bfloat16(v.y - __bfloat162float(h1));
    __nv_bfloat16 l2 = __float2bfloat16(v.z - __bfloat162float(h2));
    __nv_bfloat16 l3 = __float2bfloat16(v.w - __bfloat162float(h3));
    __nv_bfloat162* ph = (__nv_bfloat162*)(g_whi + base + i);
    __nv_bfloat162* pl = (__nv_bfloat162*)(g_wlo + base + i);
    ph[0] = __halves2bfloat162(h0, h1); ph[1] = __halves2bfloat162(h2, h3);
    pl[0] = __halves2bfloat162(l0, l1); pl[1] = __halves2bfloat162(l2, l3);
}

// ---------------------------------------------------------------------------
// bf16x3 split GEMM on mma.sync (HMMA).  C[m,n] = x[m,:] . W_z[n,:] + b_z[n]
// z: 0=q, 1=k, 2=v, 3=g(sigmoid).  CTA 128x128, BK=64, 3-stage cp.async.
// 8 warps = 2(m) x 4(n); warp tile 64x32; mma m16n8k16.
// ---------------------------------------------------------------------------
__global__ __launch_bounds__(256, 1) void gemm_mma(
    const float* __restrict__ bq, const float* __restrict__ bk,
    const float* __restrict__ bv, const float* __restrict__ bg)
{
    extern __shared__ char smem[];
    const uint32_t sb = smem_u32(smem);
    const int tid = threadIdx.x;
    const int wid = tid >> 5, lane = tid & 31;
    const int wm = wid >> 2, wn = wid & 3;           // warp coords (2 x 4)
    const int z = blockIdx.z;
    const size_t m0 = (size_t)blockIdx.y * Bb_M;
    const size_t n0 = (size_t)blockIdx.x * Bb_N;

    const float* bias = (z == 0) ? bq : (z == 1) ? bk : (z == 2) ? bv : bg;
    float* outp = (z == 0) ? g_q : (z == 1) ? g_k : (z == 2) ? g_v : g_g;

    const char* Ahi = (const char*)g_xhi + m0 * (DD * 2);
    const char* Alo = (const char*)g_xlo + m0 * (DD * 2);
    const char* Bhi = (const char*)(g_whi + (size_t)z * DD * EE) + n0 * (DD * 2);
    const char* Blo = (const char*)(g_wlo + (size_t)z * DD * EE) + n0 * (DD * 2);

    // per-thread load mapping: 16 chunks of 16B per stage (4 per matrix)
    const int lrow = tid >> 3;        // 0..31  (row block; +32*j)
    const int lch  = tid & 7;         // 0..7   (16B chunk in 128B row)

    auto load_stage = [&](int buf, int kb) {
        const uint32_t sbase = sb + buf * STAGE_BYTES;
        const size_t kbyte = (size_t)kb * 128;
        #pragma unroll
        for (int j = 0; j < 4; j++) {
            int row = lrow + j * 32;
            size_t goff = (size_t)row * (DD * 2) + kbyte + lch * 16;
            uint32_t soff = swz((uint32_t)row, (uint32_t)lch);
            cp_async16(sbase + AHI_OFF + soff, Ahi + goff);
            cp_async16(sbase + ALO_OFF + soff, Alo + goff);
            cp_async16(sbase + BHI_OFF + soff, Bhi + goff);
            cp_async16(sbase + BLO_OFF + soff, Blo + goff);
        }
    };

    float acc[4][4][4];
    #pragma unroll
    for (int mi = 0; mi < 4; mi++)
        #pragma unroll
        for (int ni = 0; ni < 4; ni++)
            #pragma unroll
            for (int e = 0; e < 4; e++) acc[mi][ni][e] = 0.f;

    load_stage(0, 0); CP_COMMIT();
    load_stage(1, 1); CP_COMMIT();

    // ldmatrix lane->row mapping
    const uint32_t arow = (uint32_t)(wm * 64) + (uint32_t)(lane & 15); // + mi*16
    const uint32_t ahib = (uint32_t)(lane >> 4);                       // chunk lsb
    const uint32_t brow = (uint32_t)(wn * 32) + (uint32_t)(lane & 7) +
                          (uint32_t)((lane & 16) >> 1);                // + grp*16
    const uint32_t bhib = (uint32_t)((lane >> 3) & 1);

    for (int kb = 0; kb < KSTAGES; kb++) {
        CP_WAIT1();
        __syncthreads();
        if (kb + 2 < KSTAGES) load_stage((kb + 2) % NSTAGE, kb + 2);
        CP_COMMIT();

        const uint32_t sbase = sb + (kb % NSTAGE) * STAGE_BYTES;
        #pragma unroll
        for (int kk = 0; kk < 4; kk++) {
            uint32_t ah[4][4], al[4][4];
            #pragma unroll
            for (int mi = 0; mi < 4; mi++) {
                uint32_t off = swz(arow + mi * 16, kk * 2 + ahib);
                ldsm4(ah[mi], sbase + AHI_OFF + off);
                ldsm4(al[mi], sbase + ALO_OFF + off);
            }
            uint32_t bh[2][4], bl[2][4];
            #pragma unroll
            for (int g = 0; g < 2; g++) {
                uint32_t off = swz(brow + g * 16, kk * 2 + bhib);
                ldsm4(bh[g], sbase + BHI_OFF + off);
                ldsm4(bl[g], sbase + BLO_OFF + off);
            }
            #pragma unroll
            for (int mi = 0; mi < 4; mi++)
                #pragma unroll
                for (int g = 0; g < 2; g++)
                    #pragma unroll
                    for (int s = 0; s < 2; s++) {
                        int ni = g * 2 + s;
                        mma16816(acc[mi][ni], ah[mi], bh[g][s*2], bh[g][s*2+1]);
                        mma16816(acc[mi][ni], ah[mi], bl[g][s*2], bl[g][s*2+1]);
                        mma16816(acc[mi][ni], al[mi], bh[g][s*2], bh[g][s*2+1]);
                    }
        }
    }

    // Epilogue: bias (+ sigmoid for z==3), float2 stores
    const int crow = lane >> 2;          // 0..7
    const int ccol = (lane & 3) * 2;     // 0,2,4,6
    #pragma unroll
    for (int ni = 0; ni < 4; ni++) {
        size_t n = n0 + wn * 32 + ni * 8 + ccol;
        float b0 = __ldg(bias + n), b1 = __ldg(bias + n + 1);
        #pragma unroll
        for (int mi = 0; mi < 4; mi++) {
            size_t m = m0 + wm * 64 + mi * 16 + crow;
            float2 o0 = make_float2(acc[mi][ni][0] + b0, acc[mi][ni][1] + b1);
            float2 o1 = make_float2(acc[mi][ni][2] + b0, acc[mi][ni][3] + b1);
            if (z == 3) {
                o0.x = 1.f/(1.f+expf(-o0.x)); o0.y = 1.f/(1.f+expf(-o0.y));
                o1.x = 1.f/(1.f+expf(-o1.x)); o1.y = 1.f/(1.f+expf(-o1.y));
            }
            *(float2*)(outp + m * (size_t)EE + n) = o0;
            *(float2*)(outp + (m + 8) * (size_t)EE + n) = o1;
        }
    }
}

// ---------------------------------------------------------------------------
// Scan pass 1: per-chunk sums of k*v
// ---------------------------------------------------------------------------
__global__ __launch_bounds__(256) void chunk_sums()
{
    const int e = blockIdx.x * 256 + threadIdx.x;
    const int c = blockIdx.y;
    const int b = blockIdx.z;
    size_t idx = ((size_t)(b * SS + c * LCHUNK)) * EE + e;
    float s = 0.f;
    #pragma unroll 8
    for (int i = 0; i < LCHUNK; i++) {
        s += g_k[idx] * g_v[idx];
        idx += EE;
    }
    g_sums[((size_t)b * EE + e) * NCHUNK + c] = s;
}

// ---------------------------------------------------------------------------
// Scan pass 2: exclusive scan of chunk sums (in place)
// ---------------------------------------------------------------------------
__global__ __launch_bounds__(256) void scan_sums()
{
    const int t = blockIdx.x * 256 + threadIdx.x;
    float* p = g_sums + (size_t)t * NCHUNK;
    float v[NCHUNK];
    #pragma unroll
    for (int c = 0; c < NCHUNK; c++) v[c] = p[c];
    float run = 0.f;
    #pragma unroll
    for (int c = 0; c < NCHUNK; c++) { float t2 = v[c]; v[c] = run; run += t2; }
    #pragma unroll
    for (int c = 0; c < NCHUNK; c++) p[c] = v[c];
}

// ---------------------------------------------------------------------------
// Scan pass 3: local inclusive scan + q * state * g
// ---------------------------------------------------------------------------
__global__ __launch_bounds__(256) void finalize(float* __restrict__ out)
{
    const int e = blockIdx.x * 256 + threadIdx.x;
    const int c = blockIdx.y;
    const int b = blockIdx.z;
    float run = g_sums[((size_t)b * EE + e) * NCHUNK + c];
    size_t idx = ((size_t)(b * SS + c * LCHUNK)) * EE + e;
    #pragma unroll 4
    for (int i = 0; i < LCHUNK; i++) {
        run += g_k[idx] * g_v[idx];
        out[idx] = g_q[idx] * run * g_g[idx];
        idx += EE;
    }
}

// ---------------------------------------------------------------------------
// Launch
// ---------------------------------------------------------------------------
extern "C" void kernel_launch(void* const* d_in, const int* in_sizes, int n_in,
                              void* d_out, int out_size)
{
    const float* x  = (const float*)d_in[0];
    const float* Wq = (const float*)d_in[1];
    const float* bq = (const float*)d_in[2];
    const float* Wk = (const float*)d_in[3];
    const float* bk = (const float*)d_in[4];
    const float* Wv = (const float*)d_in[5];
    const float* bv = (const float*)d_in[6];
    const float* Wg = (const float*)d_in[7];
    const float* bg = (const float*)d_in[8];
    float* out = (float*)d_out;

    cudaFuncSetAttribute(gemm_mma,
        cudaFuncAttributeMaxDynamicSharedMemorySize, SMEM_TOTAL);

    conv_x_kernel<<<(MM * (size_t)DD / 4) / 256, 256>>>(x);
    conv_w_kernel<<<dim3((DD * (size_t)EE / 4) / 256, 4), 256>>>(Wq, Wk, Wv, Wg);

    gemm_mma<<<dim3(EE/Bb_N, MM/Bb_M, 4), 256, SMEM_TOTAL>>>(bq, bk, bv, bg);

    dim3 gridC(EE / 256, NCHUNK, BB);
    chunk_sums<<<gridC, 256>>>();
    scan_sums<<<(BB * EE) / 256, 256>>>();
    finalize<<<gridC, 256>>>(out);
}

// round 5
// speedup vs baseline: 3.5684x; 1.0430x over previous
#include <cuda_runtime.h>
#include <cuda_bf16.h>
#include <cstdint>
#include <math.h>

// ---------------------------------------------------------------------------
// Problem dims
// ---------------------------------------------------------------------------
#define BB 4
#define SS 4096
#define DD 2048
#define EE 2048
#define MM (BB*SS)         // 16384
#define NCHUNK 64
#define LCHUNK (SS/NCHUNK) // 64

// GEMM tiling: CTA 256x128, BK=64, warps 4(m) x 2(n), warp tile 64x64
#define Bb_M 256
#define Bb_N 128
#define Bb_K 64
#define KSTAGES (DD/Bb_K)  // 32

// Stage smem layout (bytes): A 256 rows x 128B (hi,lo), B 128 rows x 128B (hi,lo)
#define AHI_OFF 0
#define ALO_OFF 32768
#define BHI_OFF 65536
#define BLO_OFF 81920
#define STAGE_BYTES 98304
#define SMEM_TOTAL (2*STAGE_BYTES)   // 196608

// ---------------------------------------------------------------------------
// Device scratch
// ---------------------------------------------------------------------------
__device__ __nv_bfloat16 g_xhi[(size_t)MM * DD];
__device__ __nv_bfloat16 g_xlo[(size_t)MM * DD];
__device__ __nv_bfloat16 g_whi[(size_t)4 * DD * EE];   // order: q,k,v,g
__device__ __nv_bfloat16 g_wlo[(size_t)4 * DD * EE];
__device__ float g_q[(size_t)MM * EE];
__device__ float g_k[(size_t)MM * EE];
__device__ float g_v[(size_t)MM * EE];
__device__ float g_g[(size_t)MM * EE];
__device__ float g_sums[(size_t)BB * EE * NCHUNK];

// ---------------------------------------------------------------------------
// Helpers (sm_80-era instructions only — compile at compute_103 baseline)
// ---------------------------------------------------------------------------
__device__ __forceinline__ uint32_t smem_u32(const void* p) {
    uint32_t a;
    asm("{ .reg .u64 t; cvta.to.shared.u64 t, %1; cvt.u32.u64 %0, t; }"
        : "=r"(a) : "l"(p));
    return a;
}
__device__ __forceinline__ void cp_async16(uint32_t dst, const void* src) {
    asm volatile("cp.async.cg.shared.global [%0], [%1], 16;"
                 :: "r"(dst), "l"(src) : "memory");
}
#define CP_COMMIT() asm volatile("cp.async.commit_group;" ::: "memory")
#define CP_WAIT1()  asm volatile("cp.async.wait_group 1;" ::: "memory")
#define CP_WAIT0()  asm volatile("cp.async.wait_group 0;" ::: "memory")

__device__ __forceinline__ void ldsm4(uint32_t (&r)[4], uint32_t addr) {
    asm volatile("ldmatrix.sync.aligned.m8n8.x4.shared.b16 {%0,%1,%2,%3}, [%4];"
                 : "=r"(r[0]), "=r"(r[1]), "=r"(r[2]), "=r"(r[3]) : "r"(addr));
}
__device__ __forceinline__ void mma16816(float (&c)[4], const uint32_t (&a)[4],
                                         uint32_t b0, uint32_t b1) {
    asm volatile("mma.sync.aligned.m16n8k16.row.col.f32.bf16.bf16.f32 "
                 "{%0,%1,%2,%3}, {%4,%5,%6,%7}, {%8,%9}, {%0,%1,%2,%3};"
                 : "+f"(c[0]), "+f"(c[1]), "+f"(c[2]), "+f"(c[3])
                 : "r"(a[0]), "r"(a[1]), "r"(a[2]), "r"(a[3]), "r"(b0), "r"(b1));
}
// SW128 swizzled byte offset inside a [row][128B] tile
__device__ __forceinline__ uint32_t swz(uint32_t row, uint32_t ch) {
    return row * 128u + (((ch ^ (row & 7u)) & 7u) << 4);
}

// ---------------------------------------------------------------------------
// fp32 -> bf16 hi/lo split conversions
// ---------------------------------------------------------------------------
__global__ __launch_bounds__(256) void conv_x_kernel(const float* __restrict__ x)
{
    size_t i = ((size_t)blockIdx.x * 256 + threadIdx.x) * 4;
    float4 v = *(const float4*)(x + i);
    __nv_bfloat16 h0 = __float2bfloat16(v.x), h1 = __float2bfloat16(v.y);
    __nv_bfloat16 h2 = __float2bfloat16(v.z), h3 = __float2bfloat16(v.w);
    __nv_bfloat16 l0 = __float2bfloat16(v.x - __bfloat162float(h0));
    __nv_bfloat16 l1 = __float2bfloat16(v.y - __bfloat162float(h1));
    __nv_bfloat16 l2 = __float2bfloat16(v.z - __bfloat162float(h2));
    __nv_bfloat16 l3 = __float2bfloat16(v.w - __bfloat162float(h3));
    __nv_bfloat162* ph = (__nv_bfloat162*)(g_xhi + i);
    __nv_bfloat162* pl = (__nv_bfloat162*)(g_xlo + i);
    ph[0] = __halves2bfloat162(h0, h1); ph[1] = __halves2bfloat162(h2, h3);
    pl[0] = __halves2bfloat162(l0, l1); pl[1] = __halves2bfloat162(l2, l3);
}

__global__ __launch_bounds__(256) void conv_w_kernel(
    const float* __restrict__ Wq, const float* __restrict__ Wk,
    const float* __restrict__ Wv, const float* __restrict__ Wg)
{
    int y = blockIdx.y;
    const float* W = (y == 0) ? Wq : (y == 1) ? Wk : (y == 2) ? Wv : Wg;
    size_t base = (size_t)y * DD * EE;
    size_t i = ((size_t)blockIdx.x * 256 + threadIdx.x) * 4;
    float4 v = *(const float4*)(W + i);
    __nv_bfloat16 h0 = __float2bfloat16(v.x), h1 = __float2bfloat16(v.y);
    __nv_bfloat16 h2 = __float2bfloat16(v.z), h3 = __float2bfloat16(v.w);
    __nv_bfloat16 l0 = __float2bfloat16(v.x - __bfloat162float(h0));
    __nv_bfloat16 l1 = __float2bfloat16(v.y - __bfloat162float(h1));
    __nv_bfloat16 l2 = __float2bfloat16(v.z - __bfloat162float(h2));
    __nv_bfloat16 l3 = __float2bfloat16(v.w - __bfloat162float(h3));
    __nv_bfloat162* ph = (__nv_bfloat162*)(g_whi + base + i);
    __nv_bfloat162* pl = (__nv_bfloat162*)(g_wlo + base + i);
    ph[0] = __halves2bfloat162(h0, h1); ph[1] = __halves2bfloat162(h2, h3);
    pl[0] = __halves2bfloat162(l0, l1); pl[1] = __halves2bfloat162(l2, l3);
}

// ---------------------------------------------------------------------------
// bf16x3 split GEMM on mma.sync.  C[m,n] = x[m,:] . W_z[n,:] + b_z[n]
// z: 0=q, 1=k, 2=v, 3=g(sigmoid).
// CTA 256x128, BK=64, 2-stage cp.async; warps 4(m) x 2(n); warp tile 64x64.
// A fragments register-resident per kk; B fragments streamed per 16-col group.
// ---------------------------------------------------------------------------
__global__ __launch_bounds__(256, 1) void gemm_mma(
    const float* __restrict__ bq, const float* __restrict__ bk,
    const float* __restrict__ bv, const float* __restrict__ bg)
{
    extern __shared__ char smem[];
    const uint32_t sb = smem_u32(smem);
    const int tid = threadIdx.x;
    const int wid = tid >> 5, lane = tid & 31;
    const int wm = wid >> 1, wn = wid & 1;           // warp coords (4 x 2)
    const int z = blockIdx.z;
    const size_t m0 = (size_t)blockIdx.y * Bb_M;
    const size_t n0 = (size_t)blockIdx.x * Bb_N;

    const float* bias = (z == 0) ? bq : (z == 1) ? bk : (z == 2) ? bv : bg;
    float* outp = (z == 0) ? g_q : (z == 1) ? g_k : (z == 2) ? g_v : g_g;

    const char* Ahi = (const char*)g_xhi + m0 * (DD * 2);
    const char* Alo = (const char*)g_xlo + m0 * (DD * 2);
    const char* Bhi = (const char*)(g_whi + (size_t)z * DD * EE) + n0 * (DD * 2);
    const char* Blo = (const char*)(g_wlo + (size_t)z * DD * EE) + n0 * (DD * 2);

    // per-thread load mapping: 24 x 16B chunks per stage
    const int lrow = tid >> 3;        // 0..31
    const int lch  = tid & 7;         // 0..7

    auto load_stage = [&](int buf, int kb) {
        const uint32_t sbase = sb + buf * STAGE_BYTES;
        const size_t kbyte = (size_t)kb * 128;
        #pragma unroll
        for (int j = 0; j < 8; j++) {          // A: 256 rows hi + lo
            int row = lrow + j * 32;
            size_t goff = (size_t)row * (DD * 2) + kbyte + lch * 16;
            uint32_t soff = swz((uint32_t)row, (uint32_t)lch);
            cp_async16(sbase + AHI_OFF + soff, Ahi + goff);
            cp_async16(sbase + ALO_OFF + soff, Alo + goff);
        }
        #pragma unroll
        for (int j = 0; j < 4; j++) {          // B: 128 rows hi + lo
            int row = lrow + j * 32;
            size_t goff = (size_t)row * (DD * 2) + kbyte + lch * 16;
            uint32_t soff = swz((uint32_t)row, (uint32_t)lch);
            cp_async16(sbase + BHI_OFF + soff, Bhi + goff);
            cp_async16(sbase + BLO_OFF + soff, Blo + goff);
        }
    };

    float acc[4][8][4];   // [mi][ni = g*2+s][frag]
    #pragma unroll
    for (int mi = 0; mi < 4; mi++)
        #pragma unroll
        for (int ni = 0; ni < 8; ni++)
            #pragma unroll
            for (int e = 0; e < 4; e++) acc[mi][ni][e] = 0.f;

    load_stage(0, 0); CP_COMMIT();

    // ldmatrix lane->row mapping
    const uint32_t arow = (uint32_t)(wm * 64) + (uint32_t)(lane & 15); // + mi*16
    const uint32_t ahib = (uint32_t)(lane >> 4);
    const uint32_t brow = (uint32_t)(wn * 64) + (uint32_t)(lane & 7) +
                          (uint32_t)((lane & 16) >> 1);                // + g*16
    const uint32_t bhib = (uint32_t)((lane >> 3) & 1);

    for (int kb = 0; kb < KSTAGES; kb++) {
        const int buf = kb & 1;
        if (kb + 1 < KSTAGES) {
            load_stage(buf ^ 1, kb + 1); CP_COMMIT();
            CP_WAIT1();
        } else {
            CP_WAIT0();
        }
        __syncthreads();

        const uint32_t sbase = sb + buf * STAGE_BYTES;
        #pragma unroll
        for (int kk = 0; kk < 4; kk++) {
            uint32_t ah[4][4], al[4][4];
            #pragma unroll
            for (int mi = 0; mi < 4; mi++) {
                uint32_t off = swz(arow + mi * 16, kk * 2 + ahib);
                ldsm4(ah[mi], sbase + AHI_OFF + off);
                ldsm4(al[mi], sbase + ALO_OFF + off);
            }
            #pragma unroll
            for (int g = 0; g < 4; g++) {       // stream B frags per 16-col group
                uint32_t bh[4], bl[4];
                uint32_t off = swz(brow + g * 16, kk * 2 + bhib);
                ldsm4(bh, sbase + BHI_OFF + off);
                ldsm4(bl, sbase + BLO_OFF + off);
                #pragma unroll
                for (int mi = 0; mi < 4; mi++) {
                    #pragma unroll
                    for (int s = 0; s < 2; s++) {
                        int ni = g * 2 + s;
                        mma16816(acc[mi][ni], ah[mi], bh[s*2], bh[s*2+1]);
                        mma16816(acc[mi][ni], ah[mi], bl[s*2], bl[s*2+1]);
                        mma16816(acc[mi][ni], al[mi], bh[s*2], bh[s*2+1]);
                    }
                }
            }
        }
        __syncthreads();
    }

    // Epilogue: bias (+ sigmoid for z==3), float2 stores
    const int crow = lane >> 2;          // 0..7
    const int ccol = (lane & 3) * 2;     // 0,2,4,6
    #pragma unroll
    for (int ni = 0; ni < 8; ni++) {
        size_t n = n0 + wn * 64 + ni * 8 + ccol;
        float b0 = __ldg(bias + n), b1 = __ldg(bias + n + 1);
        #pragma unroll
        for (int mi = 0; mi < 4; mi++) {
            size_t m = m0 + wm * 64 + mi * 16 + crow;
            float2 o0 = make_float2(acc[mi][ni][0] + b0, acc[mi][ni][1] + b1);
            float2 o1 = make_float2(acc[mi][ni][2] + b0, acc[mi][ni][3] + b1);
            if (z == 3) {
                o0.x = 1.f/(1.f+expf(-o0.x)); o0.y = 1.f/(1.f+expf(-o0.y));
                o1.x = 1.f/(1.f+expf(-o1.x)); o1.y = 1.f/(1.f+expf(-o1.y));
            }
            *(float2*)(outp + m * (size_t)EE + n) = o0;
            *(float2*)(outp + (m + 8) * (size_t)EE + n) = o1;
        }
    }
}

// ---------------------------------------------------------------------------
// Scan pass 1: per-chunk sums of k*v
// ---------------------------------------------------------------------------
__global__ __launch_bounds__(256) void chunk_sums()
{
    const int e = blockIdx.x * 256 + threadIdx.x;
    const int c = blockIdx.y;
    const int b = blockIdx.z;
    size_t idx = ((size_t)(b * SS + c * LCHUNK)) * EE + e;
    float s = 0.f;
    #pragma unroll 8
    for (int i = 0; i < LCHUNK; i++) {
        s += g_k[idx] * g_v[idx];
        idx += EE;
    }
    g_sums[((size_t)b * EE + e) * NCHUNK + c] = s;
}

// ---------------------------------------------------------------------------
// Scan pass 2: exclusive scan of chunk sums (in place)
// ---------------------------------------------------------------------------
__global__ __launch_bounds__(256) void scan_sums()
{
    const int t = blockIdx.x * 256 + threadIdx.x;
    float* p = g_sums + (size_t)t * NCHUNK;
    float v[NCHUNK];
    #pragma unroll
    for (int c = 0; c < NCHUNK; c++) v[c] = p[c];
    float run = 0.f;
    #pragma unroll
    for (int c = 0; c < NCHUNK; c++) { float t2 = v[c]; v[c] = run; run += t2; }
    #pragma unroll
    for (int c = 0; c < NCHUNK; c++) p[c] = v[c];
}

// ---------------------------------------------------------------------------
// Scan pass 3: local inclusive scan + q * state * g
// ---------------------------------------------------------------------------
__global__ __launch_bounds__(256) void finalize(float* __restrict__ out)
{
    const int e = blockIdx.x * 256 + threadIdx.x;
    const int c = blockIdx.y;
    const int b = blockIdx.z;
    float run = g_sums[((size_t)b * EE + e) * NCHUNK + c];
    size_t idx = ((size_t)(b * SS + c * LCHUNK)) * EE + e;
    #pragma unroll 4
    for (int i = 0; i < LCHUNK; i++) {
        run += g_k[idx] * g_v[idx];
        out[idx] = g_q[idx] * run * g_g[idx];
        idx += EE;
    }
}

// ---------------------------------------------------------------------------
// Launch
// ---------------------------------------------------------------------------
extern "C" void kernel_launch(void* const* d_in, const int* in_sizes, int n_in,
                              void* d_out, int out_size)
{
    const float* x  = (const float*)d_in[0];
    const float* Wq = (const float*)d_in[1];
    const float* bq = (const float*)d_in[2];
    const float* Wk = (const float*)d_in[3];
    const float* bk = (const float*)d_in[4];
    const float* Wv = (const float*)d_in[5];
    const float* bv = (const float*)d_in[6];
    const float* Wg = (const float*)d_in[7];
    const float* bg = (const float*)d_in[8];
    float* out = (float*)d_out;

    cudaFuncSetAttribute(gemm_mma,
        cudaFuncAttributeMaxDynamicSharedMemorySize, SMEM_TOTAL);

    conv_x_kernel<<<(MM * (size_t)DD / 4) / 256, 256>>>(x);
    conv_w_kernel<<<dim3((DD * (size_t)EE / 4) / 256, 4), 256>>>(Wq, Wk, Wv, Wg);

    gemm_mma<<<dim3(EE/Bb_N, MM/Bb_M, 4), 256, SMEM_TOTAL>>>(bq, bk, bv, bg);

    dim3 gridC(EE / 256, NCHUNK, BB);
    chunk_sums<<<gridC, 256>>>();
    scan_sums<<<(BB * EE) / 256, 256>>>();
    finalize<<<gridC, 256>>>(out);
}